// round 2
// baseline (speedup 1.0000x reference)
#include <cuda_runtime.h>
#include <math.h>

#define T_LEN 1024
#define KCNT  1024
#define HDIM  256
#define EDIM  64
#define TOPIC 100
#define EXLEN 768
#define GRUIN 201
#define TOPK  64

// device-global scratch (no allocation allowed)
__device__ float g_v[TOPIC];
__device__ float g_kn[EDIM];
__device__ float g_beta_all[T_LEN];
__device__ float g_alog[KCNT];
__device__ float g_gsum[3 * HDIM];
__device__ float g_beta[TOPK];
__device__ int   g_idx[TOPK];
__device__ float g_alpha[KCNT];
__device__ float g_hkp_part[8 * HDIM];   // 8 replicas to spread atomics
__device__ int   g_cntA;                 // phase-A done counter (K1)
__device__ int   g_cntB;                 // phase-B done counter (K1)
__device__ int   g_gcnt;                 // gather-block done counter (K3)
__device__ volatile int g_flag;          // sort-done flag (K3)

__device__ __forceinline__ float warpSum(float v) {
    #pragma unroll
    for (int o = 16; o > 0; o >>= 1) v += __shfl_down_sync(0xffffffffu, v, o);
    return v;
}
__device__ __forceinline__ float warpMax(float v) {
    #pragma unroll
    for (int o = 16; o > 0; o >>= 1) v = fmaxf(v, __shfl_xor_sync(0xffffffffu, v, o));
    return v;
}

// ---------------------------------------------------------------------------
// K1: phaseA (164 blocks): v = Wr@ex+br, kn = Wk@co+bk      -> g_cntA
//     phaseB (352 blocks, spin cntA): beta_all, alog, gsum  -> g_cntB
//     phaseC (1 block, spin cntB): alpha = softmax(alog)
// ---------------------------------------------------------------------------
__global__ void __launch_bounds__(256) k1(const float* __restrict__ Wr,
                                          const float* __restrict__ br,
                                          const float* __restrict__ ex,
                                          const float* __restrict__ Wk,
                                          const float* __restrict__ bk,
                                          const float* __restrict__ co,
                                          const float* __restrict__ vs,
                                          const float* __restrict__ KM,
                                          const float* __restrict__ Wih,
                                          const float* __restrict__ s_in) {
    int bid = blockIdx.x, tid = threadIdx.x;
    int warp = tid >> 5, lane = tid & 31;
    __shared__ float red[8];
    __shared__ float sx[GRUIN];
    __shared__ float sbc;

    if (bid < 164) {
        // ---- phase A ----
        float p = 0.f;
        if (bid < TOPIC) {
            const float* row = Wr + bid * EXLEN;
            for (int i = tid; i < EXLEN; i += 256) p += row[i] * ex[i];
        } else {
            int j = bid - TOPIC;
            const float* row = Wk + j * KCNT;
            for (int i = tid; i < KCNT; i += 256) p += row[i] * co[i];
        }
        p = warpSum(p);
        if (lane == 0) red[warp] = p;
        __syncthreads();
        if (tid == 0) {
            float s = 0.f;
            #pragma unroll
            for (int w = 0; w < 8; w++) s += red[w];
            if (bid < TOPIC) g_v[bid] = s + br[bid];
            else             g_kn[bid - TOPIC] = s + bk[bid - TOPIC];
            __threadfence();
            atomicAdd(&g_cntA, 1);
        }
    } else if (bid < 516) {
        // ---- phase B ----
        if (tid == 0) {
            while (((volatile int*)&g_cntA)[0] < 164) {}
            __threadfence();
        }
        __syncthreads();
        int b2 = bid - 164;
        if (b2 < 128) {
            int t = b2 * 8 + warp;
            const float* row = vs + t * TOPIC;
            float p = 0.f;
            for (int i = lane; i < TOPIC; i += 32) p += row[i] * g_v[i];
            p = warpSum(p);
            if (lane == 0) g_beta_all[t] = p;
        } else if (b2 < 256) {
            int kk = (b2 - 128) * 8 + warp;
            const float* row = KM + kk * EDIM;
            float p = row[lane] * g_kn[lane] + row[lane + 32] * g_kn[lane + 32];
            p = warpSum(p);
            if (lane == 0) g_alog[kk] = p;
        } else {
            float sval = s_in[0];
            float msk = (sval >= 0.5f) ? 1.f : 0.f;
            if (tid < TOPIC) {
                float vv = g_v[tid];
                sx[tid] = vv * msk;
                sx[tid + TOPIC] = vv * (1.f - msk);
            }
            if (tid == 0) sx[2 * TOPIC] = sval;
            __syncthreads();
            int j = (b2 - 256) * 8 + warp;
            const float* row = Wih + j * GRUIN;
            float p = 0.f;
            for (int i = lane; i < GRUIN; i += 32) p += row[i] * sx[i];
            p = warpSum(p);
            if (lane == 0) g_gsum[j] = p;
        }
        __syncthreads();
        if (tid == 0) { __threadfence(); atomicAdd(&g_cntB, 1); }
    } else {
        // ---- phase C: alpha softmax over 1024 ----
        if (tid == 0) {
            while (((volatile int*)&g_cntB)[0] < 352) {}
            __threadfence();
        }
        __syncthreads();
        float l[4];
        #pragma unroll
        for (int j = 0; j < 4; j++) l[j] = g_alog[tid + 256 * j];
        float m = fmaxf(fmaxf(l[0], l[1]), fmaxf(l[2], l[3]));
        m = warpMax(m);
        if (lane == 0) red[warp] = m;
        __syncthreads();
        if (tid == 0) {
            float mm = red[0];
            #pragma unroll
            for (int w = 1; w < 8; w++) mm = fmaxf(mm, red[w]);
            sbc = mm;
        }
        __syncthreads();
        float M = sbc;
        float e[4], es = 0.f;
        #pragma unroll
        for (int j = 0; j < 4; j++) { e[j] = expf(l[j] - M); es += e[j]; }
        es = warpSum(es);
        if (lane == 0) red[warp] = es;
        __syncthreads();
        if (tid == 0) {
            float ss = 0.f;
            #pragma unroll
            for (int w = 0; w < 8; w++) ss += red[w];
            sbc = ss;
        }
        __syncthreads();
        float inv = 1.f / sbc;
        #pragma unroll
        for (int j = 0; j < 4; j++) g_alpha[tid + 256 * j] = e[j] * inv;
    }
}

// ---------------------------------------------------------------------------
// K3: bid 0        : bitonic top-64 + softmax -> beta/idx, set flag
//     b%9==0       : GRU tile (256 tiles) — no dependency on sort
//     else         : gather chunk (2048 blocks, spin flag), float4 streaming
//     last gather  : final score + reset counters/parts for next replay
// ---------------------------------------------------------------------------
struct SharedK3 {
    union {
        struct { float As[16][32]; float Bs[3][64][33]; } gru;
        struct { float sv[1024]; int si[1024]; float sexp[64]; float ssum; } sort;
        struct { float salpha[32]; float4 part4[4 * 64]; } gat;
    } u;
};

__global__ void __launch_bounds__(256) k3(const float* __restrict__ hs,
                                          const float* __restrict__ h0,
                                          const float* __restrict__ Whh,
                                          const float* __restrict__ bih,
                                          const float* __restrict__ bhh,
                                          const float* __restrict__ Wsc,
                                          const float* __restrict__ bsc,
                                          float* __restrict__ out) {
    __shared__ SharedK3 sm;
    __shared__ int s_last;
    __shared__ float red2[8];
    int bid = blockIdx.x, tid = threadIdx.x;

    if (bid == 0) {
        // ---------------- sorter ----------------
        for (int e = tid; e < 1024; e += 256) {
            sm.u.sort.sv[e] = g_beta_all[e];
            sm.u.sort.si[e] = e;
        }
        __syncthreads();
        for (int size = 2; size <= 1024; size <<= 1) {
            for (int stride = size >> 1; stride > 0; stride >>= 1) {
                for (int e = tid; e < 1024; e += 256) {
                    int j = e ^ stride;
                    if (j > e) {
                        float v1 = sm.u.sort.sv[e], v2 = sm.u.sort.sv[j];
                        bool up = ((e & size) == 0);
                        if (up ? (v1 < v2) : (v1 > v2)) {
                            sm.u.sort.sv[e] = v2; sm.u.sort.sv[j] = v1;
                            int t = sm.u.sort.si[e];
                            sm.u.sort.si[e] = sm.u.sort.si[j];
                            sm.u.sort.si[j] = t;
                        }
                    }
                }
                __syncthreads();
            }
        }
        float mx = sm.u.sort.sv[0];
        if (tid < TOPK) sm.u.sort.sexp[tid] = expf(sm.u.sort.sv[tid] - mx);
        __syncthreads();
        if (tid == 0) {
            float s = 0.f;
            for (int i = 0; i < TOPK; i++) s += sm.u.sort.sexp[i];
            sm.u.sort.ssum = s;
        }
        __syncthreads();
        if (tid < TOPK) {
            g_beta[tid] = sm.u.sort.sexp[tid] / sm.u.sort.ssum;
            g_idx[tid]  = sm.u.sort.si[tid];
        }
        __syncthreads();
        if (tid == 0) { __threadfence(); g_flag = 1; }
        return;
    }

    int b = bid - 1;
    if (b % 9 == 0) {
        // ---------------- GRU tile ----------------
        int id = b / 9;
        int rc = id & 63, ccb = id >> 6;
        int k0 = rc * 16, c0 = ccb * 64;
        int tx = tid & 63, ty = tid >> 6;
        float acc0[4] = {0, 0, 0, 0};
        float acc1[4] = {0, 0, 0, 0};
        float acc2[4] = {0, 0, 0, 0};
        int r = tid >> 5, dd = tid & 31;
        for (int d0 = 0; d0 < HDIM; d0 += 32) {
            sm.u.gru.As[r][dd]     = h0[(k0 + r) * HDIM + d0 + dd];
            sm.u.gru.As[r + 8][dd] = h0[(k0 + r + 8) * HDIM + d0 + dd];
            #pragma unroll
            for (int g = 0; g < 3; g++) {
                #pragma unroll
                for (int it = 0; it < 8; it++) {
                    int row = r + it * 8;
                    sm.u.gru.Bs[g][row][dd] = Whh[(g * HDIM + c0 + row) * HDIM + d0 + dd];
                }
            }
            __syncthreads();
            #pragma unroll 8
            for (int dd2 = 0; dd2 < 32; dd2++) {
                float b0 = sm.u.gru.Bs[0][tx][dd2];
                float b1 = sm.u.gru.Bs[1][tx][dd2];
                float b2 = sm.u.gru.Bs[2][tx][dd2];
                #pragma unroll
                for (int m = 0; m < 4; m++) {
                    float a = sm.u.gru.As[ty + 4 * m][dd2];
                    acc0[m] += a * b0;
                    acc1[m] += a * b1;
                    acc2[m] += a * b2;
                }
            }
            __syncthreads();
        }
        int c = c0 + tx;
        float gs_r = g_gsum[c],  gs_z = g_gsum[HDIM + c],  gs_n = g_gsum[2 * HDIM + c];
        float bi_r = bih[c],     bi_z = bih[HDIM + c],     bi_n = bih[2 * HDIM + c];
        float bh_r = bhh[c],     bh_z = bhh[HDIM + c],     bh_n = bhh[2 * HDIM + c];
        #pragma unroll
        for (int m = 0; m < 4; m++) {
            int k = k0 + ty + 4 * m;
            float al = g_alpha[k];
            float rg = 1.f / (1.f + expf(-(al * gs_r + bi_r + acc0[m] + bh_r)));
            float zg = 1.f / (1.f + expf(-(al * gs_z + bi_z + acc1[m] + bh_z)));
            float ng = tanhf(al * gs_n + bi_n + rg * (acc2[m] + bh_n));
            float hv = h0[k * HDIM + c];
            out[1 + k * HDIM + c] = (1.f - zg) * ng + zg * hv;
        }
    } else {
        // ---------------- gather chunk ----------------
        int gid = b - b / 9 - 1;          // 0..2047
        int i = gid >> 5;                 // topk index 0..63
        int ch = gid & 31;                // 32-row chunk 0..31
        int kb = ch * 32;
        int col4 = tid & 63, rgrp = tid >> 6;

        if (tid < 32) sm.u.gat.salpha[tid] = g_alpha[kb + tid];  // ready pre-flag
        if (tid == 0) { while (g_flag == 0) {} }
        __syncthreads();

        int t = g_idx[i];
        float betai = g_beta[i];
        const float* base = hs + (size_t)t * (KCNT * HDIM) + (size_t)kb * HDIM + col4 * 4;
        float4 acc = make_float4(0.f, 0.f, 0.f, 0.f);
        #pragma unroll
        for (int it = 0; it < 8; it++) {
            int rr = rgrp * 8 + it;
            float4 vv = *(const float4*)(base + (size_t)rr * HDIM);
            float a = sm.u.gat.salpha[rr];
            acc.x += a * vv.x; acc.y += a * vv.y;
            acc.z += a * vv.z; acc.w += a * vv.w;
        }
        sm.u.gat.part4[rgrp * 64 + col4] = acc;
        __syncthreads();
        const float* pf = (const float*)sm.u.gat.part4;
        float sum = pf[tid] + pf[256 + tid] + pf[512 + tid] + pf[768 + tid];
        atomicAdd(&g_hkp_part[(gid & 7) * HDIM + tid], betai * sum);
        __threadfence();
        if (tid == 0) s_last = (atomicAdd(&g_gcnt, 1) == 2047) ? 1 : 0;
        __syncthreads();
        if (s_last) {
            // ---- final score + reset ----
            float hk = 0.f;
            #pragma unroll
            for (int rr = 0; rr < 8; rr++) hk += g_hkp_part[rr * HDIM + tid];
            float p = Wsc[TOPIC + tid] * hk;
            if (tid < TOPIC) p += Wsc[tid] * g_v[tid];
            p = warpSum(p);
            if ((tid & 31) == 0) red2[tid >> 5] = p;
            __syncthreads();
            if (tid == 0) {
                float s2 = 0.f;
                #pragma unroll
                for (int w = 0; w < 8; w++) s2 += red2[w];
                out[0] = s2 + bsc[0];
                g_cntA = 0; g_cntB = 0; g_gcnt = 0; g_flag = 0;
            }
            #pragma unroll
            for (int rr = 0; rr < 8; rr++) g_hkp_part[rr * HDIM + tid] = 0.f;
        }
    }
}

extern "C" void kernel_launch(void* const* d_in, const int* in_sizes, int n_in,
                              void* d_out, int out_size) {
    const float* co_e = (const float*)d_in[0];
    const float* ex_e = (const float*)d_in[1];
    const float* s    = (const float*)d_in[2];
    const float* h    = (const float*)d_in[3];
    const float* vs   = (const float*)d_in[4];
    const float* hs   = (const float*)d_in[5];
    const float* Wr   = (const float*)d_in[6];
    const float* br   = (const float*)d_in[7];
    const float* Wk   = (const float*)d_in[8];
    const float* bk   = (const float*)d_in[9];
    const float* KM   = (const float*)d_in[10];
    const float* Wsc  = (const float*)d_in[11];
    const float* bsc  = (const float*)d_in[12];
    const float* Wih  = (const float*)d_in[13];
    const float* Whh  = (const float*)d_in[14];
    const float* bih  = (const float*)d_in[15];
    const float* bhh  = (const float*)d_in[16];
    float* out = (float*)d_out;

    k1<<<517, 256>>>(Wr, br, ex_e, Wk, bk, co_e, vs, KM, Wih, s);
    k3<<<2305, 256>>>(hs, h, Whh, bih, bhh, Wsc, bsc, out);
}

// round 10
// speedup vs baseline: 1.3323x; 1.3323x over previous
#include <cuda_runtime.h>
#include <math.h>

#define T_LEN 1024
#define KCNT  1024
#define HDIM  256
#define EDIM  64
#define TOPIC 100
#define EXLEN 768
#define GRUIN 201
#define TOPK  64

// device-global scratch (no allocation allowed)
__device__ float g_v[TOPIC];
__device__ float g_kn[EDIM];
__device__ float g_beta_all[T_LEN];
__device__ float g_alog[KCNT];
__device__ float g_gsum[3 * HDIM];
__device__ float g_beta[TOPK];
__device__ int   g_idx[TOPK];
__device__ float g_alpha[KCNT];
__device__ float g_hkp_part[8 * HDIM];
__device__ int   g_cntAv;   // v rows done (100)
__device__ int   g_cntAk;   // kn rows done (64)
__device__ int   g_cntV;    // beta_all blocks done (128)
__device__ int   g_cntL;    // alog blocks done (128)
__device__ int   g_gcnt;    // gather blocks done (k2)

__device__ __forceinline__ float warpSum(float v) {
    #pragma unroll
    for (int o = 16; o > 0; o >>= 1) v += __shfl_down_sync(0xffffffffu, v, o);
    return v;
}
__device__ __forceinline__ float warpMax(float v) {
    #pragma unroll
    for (int o = 16; o > 0; o >>= 1) v = fmaxf(v, __shfl_xor_sync(0xffffffffu, v, o));
    return v;
}

// ---------------------------------------------------------------------------
// K1:  bids 0..99    : v rows            -> cntAv
//      bids 100..163 : kn rows           -> cntAk
//      bids 164..291 : beta_all (spin Av)-> cntV
//      bids 292..419 : alog     (spin Ak)-> cntL
//      bids 420..515 : gsum     (spin Av)
//      bid  516      : alpha softmax (spin L)
//      bid  517      : radix-select top-64 + softmax (spin V)
// ---------------------------------------------------------------------------
__global__ void __launch_bounds__(256) k1(const float* __restrict__ Wr,
                                          const float* __restrict__ br,
                                          const float* __restrict__ ex,
                                          const float* __restrict__ Wk,
                                          const float* __restrict__ bk,
                                          const float* __restrict__ co,
                                          const float* __restrict__ vs,
                                          const float* __restrict__ KM,
                                          const float* __restrict__ Wih,
                                          const float* __restrict__ s_in) {
    int bid = blockIdx.x, tid = threadIdx.x;
    int warp = tid >> 5, lane = tid & 31;
    __shared__ float red[8];

    if (bid < 164) {
        // ---- phase A: v / kn rows ----
        float p = 0.f;
        if (bid < TOPIC) {
            const float* row = Wr + bid * EXLEN;
            for (int i = tid; i < EXLEN; i += 256) p += row[i] * ex[i];
        } else {
            int j = bid - TOPIC;
            const float* row = Wk + j * KCNT;
            for (int i = tid; i < KCNT; i += 256) p += row[i] * co[i];
        }
        p = warpSum(p);
        if (lane == 0) red[warp] = p;
        __syncthreads();
        if (tid == 0) {
            float s = 0.f;
            #pragma unroll
            for (int w = 0; w < 8; w++) s += red[w];
            if (bid < TOPIC) { g_v[bid] = s + br[bid]; __threadfence(); atomicAdd(&g_cntAv, 1); }
            else { g_kn[bid - TOPIC] = s + bk[bid - TOPIC]; __threadfence(); atomicAdd(&g_cntAk, 1); }
        }
    } else if (bid < 292) {
        // ---- beta_all = vs @ v ----
        if (tid == 0) { while (((volatile int*)&g_cntAv)[0] < TOPIC) {} __threadfence(); }
        __syncthreads();
        int t = (bid - 164) * 8 + warp;
        const float* row = vs + t * TOPIC;
        float p = 0.f;
        for (int i = lane; i < TOPIC; i += 32) p += row[i] * g_v[i];
        p = warpSum(p);
        if (lane == 0) g_beta_all[t] = p;
        __syncthreads();
        if (tid == 0) { __threadfence(); atomicAdd(&g_cntV, 1); }
    } else if (bid < 420) {
        // ---- alog = KM @ kn ----
        if (tid == 0) { while (((volatile int*)&g_cntAk)[0] < EDIM) {} __threadfence(); }
        __syncthreads();
        int kk = (bid - 292) * 8 + warp;
        const float* row = KM + kk * EDIM;
        float p = row[lane] * g_kn[lane] + row[lane + 32] * g_kn[lane + 32];
        p = warpSum(p);
        if (lane == 0) g_alog[kk] = p;
        __syncthreads();
        if (tid == 0) { __threadfence(); atomicAdd(&g_cntL, 1); }
    } else if (bid < 516) {
        // ---- gsum = W_ih @ x ----
        __shared__ float sx[GRUIN];
        if (tid == 0) { while (((volatile int*)&g_cntAv)[0] < TOPIC) {} __threadfence(); }
        __syncthreads();
        float sval = s_in[0];
        float msk = (sval >= 0.5f) ? 1.f : 0.f;
        if (tid < TOPIC) {
            float vv = g_v[tid];
            sx[tid] = vv * msk;
            sx[tid + TOPIC] = vv * (1.f - msk);
        }
        if (tid == 0) sx[2 * TOPIC] = sval;
        __syncthreads();
        int j = (bid - 420) * 8 + warp;
        const float* row = Wih + j * GRUIN;
        float p = 0.f;
        for (int i = lane; i < GRUIN; i += 32) p += row[i] * sx[i];
        p = warpSum(p);
        if (lane == 0) g_gsum[j] = p;
    } else if (bid == 516) {
        // ---- alpha = softmax(alog) ----
        __shared__ float sbc;
        if (tid == 0) { while (((volatile int*)&g_cntL)[0] < 128) {} __threadfence(); }
        __syncthreads();
        float l[4];
        #pragma unroll
        for (int j = 0; j < 4; j++) l[j] = g_alog[tid + 256 * j];
        float m = fmaxf(fmaxf(l[0], l[1]), fmaxf(l[2], l[3]));
        m = warpMax(m);
        if (lane == 0) red[warp] = m;
        __syncthreads();
        if (tid == 0) {
            float mm = red[0];
            #pragma unroll
            for (int w = 1; w < 8; w++) mm = fmaxf(mm, red[w]);
            sbc = mm;
        }
        __syncthreads();
        float M = sbc;
        float e[4], es = 0.f;
        #pragma unroll
        for (int j = 0; j < 4; j++) { e[j] = expf(l[j] - M); es += e[j]; }
        es = warpSum(es);
        if (lane == 0) red[warp] = es;
        __syncthreads();
        if (tid == 0) {
            float ss = 0.f;
            #pragma unroll
            for (int w = 0; w < 8; w++) ss += red[w];
            sbc = ss;
        }
        __syncthreads();
        float inv = 1.f / sbc;
        #pragma unroll
        for (int j = 0; j < 4; j++) g_alpha[tid + 256 * j] = e[j] * inv;
    } else {
        // ---- radix-select top-64 + softmax ----
        __shared__ int sc[32];
        __shared__ int sslot;
        __shared__ float sval[TOPK];
        __shared__ int   sidx[TOPK];
        __shared__ float sred[4];
        if (tid == 0) { while (((volatile int*)&g_cntV)[0] < 128) {} __threadfence(); }
        if (tid < 32) sc[tid] = 0;
        if (tid == 0) sslot = 0;
        __syncthreads();
        unsigned key[4]; float val[4];
        #pragma unroll
        for (int j = 0; j < 4; j++) {
            float f = g_beta_all[tid + 256 * j];
            val[j] = f;
            unsigned u = __float_as_uint(f);
            key[j] = (u & 0x80000000u) ? ~u : (u | 0x80000000u);
        }
        unsigned T = 0;
        #pragma unroll
        for (int bit = 31; bit >= 0; bit--) {
            unsigned cand = T | (1u << bit);
            int c = (key[0] >= cand) + (key[1] >= cand) + (key[2] >= cand) + (key[3] >= cand);
            c = __reduce_add_sync(0xffffffffu, c);
            if (lane == 0) atomicAdd(&sc[bit], c);
            __syncthreads();
            if (sc[bit] >= TOPK) T = cand;
        }
        #pragma unroll
        for (int j = 0; j < 4; j++) {
            if (key[j] > T) {
                int p = atomicAdd(&sslot, 1);
                sval[p] = val[j]; sidx[p] = tid + 256 * j;
            }
        }
        __syncthreads();
        #pragma unroll
        for (int j = 0; j < 4; j++) {
            if (key[j] == T) {
                int p = atomicAdd(&sslot, 1);
                if (p < TOPK) { sval[p] = val[j]; sidx[p] = tid + 256 * j; }
            }
        }
        __syncthreads();
        if (tid < TOPK) {
            float m = warpMax(sval[tid]);
            if (lane == 0) sred[tid >> 5] = m;
        }
        __syncthreads();
        float M2 = fmaxf(sred[0], sred[1]);
        float e2 = 0.f;
        if (tid < TOPK) {
            e2 = expf(sval[tid] - M2);
            float ss = warpSum(e2);
            if (lane == 0) sred[2 + (tid >> 5)] = ss;
        }
        __syncthreads();
        if (tid < TOPK) {
            g_beta[tid] = e2 / (sred[2] + sred[3]);
            g_idx[tid]  = sidx[tid];
        }
    }
}

// ---------------------------------------------------------------------------
// K2: bid % 17 == 0 : GRU GEMM tile 64k x 32c x 3gates (128 blocks)
//     else          : gather chunk (2048 blocks), float4 streaming
//     last gather   : final score + counter reset
// ---------------------------------------------------------------------------
__global__ void __launch_bounds__(256) k2(const float* __restrict__ hs,
                                          const float* __restrict__ h0,
                                          const float* __restrict__ Whh,
                                          const float* __restrict__ bih,
                                          const float* __restrict__ bhh,
                                          const float* __restrict__ Wsc,
                                          const float* __restrict__ bsc,
                                          float* __restrict__ out) {
    __shared__ union {
        struct { float As[16][68]; float Bs[3][16][36]; } g;
        struct { float salpha[32]; float4 part4[256]; } ga;
    } sm;
    __shared__ int s_last;
    __shared__ float red2[8];
    int bid = blockIdx.x, tid = threadIdx.x;

    if (bid % 17 == 0) {
        // ---------------- GEMM tile: 64 k-rows x 32 cols x 3 gates ----------------
        int id = bid / 17;                 // 0..127
        int k0 = (id & 15) * 64;
        int c0 = (id >> 4) * 32;
        int tx = tid & 15, ty = tid >> 4;
        int tx2 = tx * 2, ty4 = ty * 4;

        // A loader: 256 float4 loads (64 rows x 4 k-quads)
        int am = tid >> 2, adq = tid & 3;
        // B loader: 384 float4 loads (3 gates x 32 rows x 4 k-quads); each
        // thread handles elements tid and tid+256 (second active for tid<128)
        int l0 = tid, l1 = tid + 256;
        int bg0 = l0 >> 7, br0 = (l0 >> 2) & 31, bq0 = l0 & 3;
        int bg1 = l1 >> 7, br1 = (l1 >> 2) & 31, bq1 = l1 & 3;
        bool bact1 = (tid < 128);

        float acc[3][8];
        #pragma unroll
        for (int g = 0; g < 3; g++)
            #pragma unroll
            for (int q = 0; q < 8; q++) acc[g][q] = 0.f;

        const float* aptr  = h0 + (k0 + am) * HDIM + adq * 4;
        const float* bptr0 = Whh + (bg0 * HDIM + c0 + br0) * HDIM + bq0 * 4;
        const float* bptr1 = Whh + (bg1 * HDIM + c0 + br1) * HDIM + bq1 * 4;

        float4 av  = *(const float4*)(aptr);
        float4 bv0 = *(const float4*)(bptr0);
        float4 bv1 = bact1 ? *(const float4*)(bptr1) : make_float4(0, 0, 0, 0);

        for (int kk = 0; kk < 16; kk++) {
            sm.g.As[adq * 4 + 0][am] = av.x;
            sm.g.As[adq * 4 + 1][am] = av.y;
            sm.g.As[adq * 4 + 2][am] = av.z;
            sm.g.As[adq * 4 + 3][am] = av.w;
            sm.g.Bs[bg0][bq0 * 4 + 0][br0] = bv0.x;
            sm.g.Bs[bg0][bq0 * 4 + 1][br0] = bv0.y;
            sm.g.Bs[bg0][bq0 * 4 + 2][br0] = bv0.z;
            sm.g.Bs[bg0][bq0 * 4 + 3][br0] = bv0.w;
            if (bact1) {
                sm.g.Bs[bg1][bq1 * 4 + 0][br1] = bv1.x;
                sm.g.Bs[bg1][bq1 * 4 + 1][br1] = bv1.y;
                sm.g.Bs[bg1][bq1 * 4 + 2][br1] = bv1.z;
                sm.g.Bs[bg1][bq1 * 4 + 3][br1] = bv1.w;
            }
            __syncthreads();
            if (kk < 15) {
                av  = *(const float4*)(aptr + (kk + 1) * 16);
                bv0 = *(const float4*)(bptr0 + (kk + 1) * 16);
                if (bact1) bv1 = *(const float4*)(bptr1 + (kk + 1) * 16);
            }
            #pragma unroll
            for (int d = 0; d < 16; d++) {
                float4 a4 = *(const float4*)&sm.g.As[d][ty4];
                float2 b0 = *(const float2*)&sm.g.Bs[0][d][tx2];
                float2 b1 = *(const float2*)&sm.g.Bs[1][d][tx2];
                float2 b2 = *(const float2*)&sm.g.Bs[2][d][tx2];
                float a[4] = {a4.x, a4.y, a4.z, a4.w};
                #pragma unroll
                for (int m = 0; m < 4; m++) {
                    acc[0][m * 2 + 0] += a[m] * b0.x;
                    acc[0][m * 2 + 1] += a[m] * b0.y;
                    acc[1][m * 2 + 0] += a[m] * b1.x;
                    acc[1][m * 2 + 1] += a[m] * b1.y;
                    acc[2][m * 2 + 0] += a[m] * b2.x;
                    acc[2][m * 2 + 1] += a[m] * b2.y;
                }
            }
            __syncthreads();
        }

        // epilogue
        #pragma unroll
        for (int cc = 0; cc < 2; cc++) {
            int c = c0 + tx2 + cc;
            float gsr = g_gsum[c],  gsz = g_gsum[HDIM + c],  gsn = g_gsum[2 * HDIM + c];
            float bir = bih[c],     biz = bih[HDIM + c],     bin_ = bih[2 * HDIM + c];
            float bhr = bhh[c],     bhz = bhh[HDIM + c],     bhn = bhh[2 * HDIM + c];
            #pragma unroll
            for (int m = 0; m < 4; m++) {
                int k = k0 + ty4 + m;
                float al = g_alpha[k];
                float rg = 1.f / (1.f + expf(-(al * gsr + bir + acc[0][m * 2 + cc] + bhr)));
                float zg = 1.f / (1.f + expf(-(al * gsz + biz + acc[1][m * 2 + cc] + bhz)));
                float ng = tanhf(al * gsn + bin_ + rg * (acc[2][m * 2 + cc] + bhn));
                float hv = h0[k * HDIM + c];
                out[1 + k * HDIM + c] = (1.f - zg) * ng + zg * hv;
            }
        }
    } else {
        // ---------------- gather chunk ----------------
        int gid = bid - bid / 17 - 1;      // 0..2047
        int i = gid >> 5;                  // topk index
        int ch = gid & 31;                 // 32-row chunk
        int kb = ch * 32;
        int col4 = tid & 63, rgrp = tid >> 6;

        if (tid < 32) sm.ga.salpha[tid] = g_alpha[kb + tid];
        __syncthreads();

        int t = g_idx[i];
        float betai = g_beta[i];
        const float* base = hs + (size_t)t * (KCNT * HDIM) + (size_t)kb * HDIM + col4 * 4;
        float4 acc = make_float4(0.f, 0.f, 0.f, 0.f);
        #pragma unroll
        for (int it = 0; it < 8; it++) {
            int rr = rgrp * 8 + it;
            float4 vv = *(const float4*)(base + (size_t)rr * HDIM);
            float a = sm.ga.salpha[rr];
            acc.x += a * vv.x; acc.y += a * vv.y;
            acc.z += a * vv.z; acc.w += a * vv.w;
        }
        sm.ga.part4[rgrp * 64 + col4] = acc;
        __syncthreads();
        const float* pf = (const float*)sm.ga.part4;
        float sum = pf[tid] + pf[256 + tid] + pf[512 + tid] + pf[768 + tid];
        atomicAdd(&g_hkp_part[(gid & 7) * HDIM + tid], betai * sum);
        __threadfence();
        if (tid == 0) s_last = (atomicAdd(&g_gcnt, 1) == 2047) ? 1 : 0;
        __syncthreads();
        if (s_last) {
            __threadfence();
            float hk = 0.f;
            #pragma unroll
            for (int rr = 0; rr < 8; rr++) hk += __ldcg(&g_hkp_part[rr * HDIM + tid]);
            float p = Wsc[TOPIC + tid] * hk;
            if (tid < TOPIC) p += Wsc[tid] * g_v[tid];
            p = warpSum(p);
            if ((tid & 31) == 0) red2[tid >> 5] = p;
            __syncthreads();
            if (tid == 0) {
                float s2 = 0.f;
                #pragma unroll
                for (int w = 0; w < 8; w++) s2 += red2[w];
                out[0] = s2 + bsc[0];
                g_cntAv = 0; g_cntAk = 0; g_cntV = 0; g_cntL = 0; g_gcnt = 0;
            }
            #pragma unroll
            for (int rr = 0; rr < 8; rr++) g_hkp_part[rr * HDIM + tid] = 0.f;
        }
    }
}

extern "C" void kernel_launch(void* const* d_in, const int* in_sizes, int n_in,
                              void* d_out, int out_size) {
    const float* co_e = (const float*)d_in[0];
    const float* ex_e = (const float*)d_in[1];
    const float* s    = (const float*)d_in[2];
    const float* h    = (const float*)d_in[3];
    const float* vs   = (const float*)d_in[4];
    const float* hs   = (const float*)d_in[5];
    const float* Wr   = (const float*)d_in[6];
    const float* br   = (const float*)d_in[7];
    const float* Wk   = (const float*)d_in[8];
    const float* bk   = (const float*)d_in[9];
    const float* KM   = (const float*)d_in[10];
    const float* Wsc  = (const float*)d_in[11];
    const float* bsc  = (const float*)d_in[12];
    const float* Wih  = (const float*)d_in[13];
    const float* Whh  = (const float*)d_in[14];
    const float* bih  = (const float*)d_in[15];
    const float* bhh  = (const float*)d_in[16];
    float* out = (float*)d_out;

    k1<<<518, 256>>>(Wr, br, ex_e, Wk, bk, co_e, vs, KM, Wih, s);
    k2<<<2176, 256>>>(hs, h, Whh, bih, bhh, Wsc, bsc, out);
}

// round 14
// speedup vs baseline: 2.1767x; 1.6338x over previous
#include <cuda_runtime.h>
#include <math.h>

#define T_LEN 1024
#define KCNT  1024
#define HDIM  256
#define EDIM  64
#define TOPIC 100
#define EXLEN 768
#define GRUIN 201
#define TOPK  64
#define NG    128                 // GEMM blocks
#define NGATH 2048                // gather blocks
#define BID_GEMM 518
#define BID_GATH (BID_GEMM + NG)  // 646
#define GRID (BID_GATH + NGATH)   // 2694

// device-global scratch (no allocation allowed)
__device__ float g_v[TOPIC];
__device__ float g_kn[EDIM];
__device__ float g_beta_all[T_LEN];
__device__ float g_alog[KCNT];
__device__ float g_gsum[3 * HDIM];
__device__ float g_beta[TOPK];
__device__ int   g_idx[TOPK];
__device__ float g_alpha[KCNT];
__device__ float g_hkp_part[8 * HDIM];
__device__ int   g_cntAv;     // v rows done (100)
__device__ int   g_cntAk;     // kn rows done (64)
__device__ int   g_cntV;      // beta_all blocks done (128)
__device__ int   g_cntL;      // alog blocks done (128)
__device__ int   g_cntG;      // gsum blocks done (96)
__device__ int   g_fAlpha;    // alpha ready
__device__ int   g_fTop;      // topk ready
__device__ int   g_gcnt;      // gather blocks done
__device__ int   g_gemmDone;  // gemm blocks done

__device__ __forceinline__ float warpSum(float v) {
    #pragma unroll
    for (int o = 16; o > 0; o >>= 1) v += __shfl_down_sync(0xffffffffu, v, o);
    return v;
}
__device__ __forceinline__ float warpMax(float v) {
    #pragma unroll
    for (int o = 16; o > 0; o >>= 1) v = fmaxf(v, __shfl_xor_sync(0xffffffffu, v, o));
    return v;
}
#define VLOAD(x) (((volatile int*)&(x))[0])

// Shared scratch: union keeps the GEMM tile (float4-LDS'd) and gather part4
// 16-byte aligned — the float4 member forces union alignment to 16.
union SharedU {
    struct {
        float red[8];
        float sx[GRUIN];
        float sbc;
        int   sc[32];
        int   sslot;
        float sval[TOPK];
        int   sidx[TOPK];
        float sred[4];
    } ph;
    struct {
        float As[16][68];      // offset 0   -> 16-aligned
        float Bs[3][16][36];   // offset 4352 -> 16-aligned
    } g;
    struct {
        float4 part4[256];     // offset 0 -> 16-aligned
        float  salpha[32];
    } ga;
};

// ---------------------------------------------------------------------------
// Single fused kernel. Bid layout (dependencies strictly lower-bid -> safe):
//   0..99    v rows          -> cntAv
//   100..163 kn rows         -> cntAk
//   164..291 beta_all        (spin Av) -> cntV
//   292..419 alog            (spin Ak) -> cntL
//   420..515 gsum            (spin Av) -> cntG
//   516      alpha softmax   (spin L)  -> fAlpha
//   517      radix top-64    (spin V)  -> fTop
//   518..645 GRU GEMM tile   (spin cntG+fAlpha at epilogue) -> gemmDone
//   646..2693 gather chunk   (spin fTop+fAlpha); last: score + reset
// ---------------------------------------------------------------------------
__global__ void __launch_bounds__(256) fused(
        const float* __restrict__ Wr,  const float* __restrict__ br,
        const float* __restrict__ ex,  const float* __restrict__ Wk,
        const float* __restrict__ bk,  const float* __restrict__ co,
        const float* __restrict__ vs,  const float* __restrict__ KM,
        const float* __restrict__ Wih, const float* __restrict__ s_in,
        const float* __restrict__ hs,  const float* __restrict__ h0,
        const float* __restrict__ Whh, const float* __restrict__ bih,
        const float* __restrict__ bhh, const float* __restrict__ Wsc,
        const float* __restrict__ bsc, float* __restrict__ out) {
    int bid = blockIdx.x, tid = threadIdx.x;
    int warp = tid >> 5, lane = tid & 31;
    __shared__ SharedU u;
    __shared__ int   s_last;
    __shared__ float red2[8];

    if (bid < 164) {
        // ---- phase A: v / kn rows ----
        float p = 0.f;
        if (bid < TOPIC) {
            const float* row = Wr + bid * EXLEN;
            for (int i = tid; i < EXLEN; i += 256) p += row[i] * ex[i];
        } else {
            int j = bid - TOPIC;
            const float* row = Wk + j * KCNT;
            for (int i = tid; i < KCNT; i += 256) p += row[i] * co[i];
        }
        p = warpSum(p);
        if (lane == 0) u.ph.red[warp] = p;
        __syncthreads();
        if (tid == 0) {
            float s = 0.f;
            #pragma unroll
            for (int w = 0; w < 8; w++) s += u.ph.red[w];
            if (bid < TOPIC) { g_v[bid] = s + br[bid]; __threadfence(); atomicAdd(&g_cntAv, 1); }
            else { g_kn[bid - TOPIC] = s + bk[bid - TOPIC]; __threadfence(); atomicAdd(&g_cntAk, 1); }
        }
    } else if (bid < 292) {
        // ---- beta_all = vs @ v ----
        if (tid == 0) { while (VLOAD(g_cntAv) < TOPIC) {} __threadfence(); }
        __syncthreads();
        int t = (bid - 164) * 8 + warp;
        const float* row = vs + t * TOPIC;
        float p = 0.f;
        for (int i = lane; i < TOPIC; i += 32) p += row[i] * g_v[i];
        p = warpSum(p);
        if (lane == 0) g_beta_all[t] = p;
        __syncthreads();
        if (tid == 0) { __threadfence(); atomicAdd(&g_cntV, 1); }
    } else if (bid < 420) {
        // ---- alog = KM @ kn ----
        if (tid == 0) { while (VLOAD(g_cntAk) < EDIM) {} __threadfence(); }
        __syncthreads();
        int kk = (bid - 292) * 8 + warp;
        const float* row = KM + kk * EDIM;
        float p = row[lane] * g_kn[lane] + row[lane + 32] * g_kn[lane + 32];
        p = warpSum(p);
        if (lane == 0) g_alog[kk] = p;
        __syncthreads();
        if (tid == 0) { __threadfence(); atomicAdd(&g_cntL, 1); }
    } else if (bid < 516) {
        // ---- gsum = W_ih @ x ----
        if (tid == 0) { while (VLOAD(g_cntAv) < TOPIC) {} __threadfence(); }
        __syncthreads();
        float sv2 = s_in[0];
        float msk = (sv2 >= 0.5f) ? 1.f : 0.f;
        if (tid < TOPIC) {
            float vv = g_v[tid];
            u.ph.sx[tid] = vv * msk;
            u.ph.sx[tid + TOPIC] = vv * (1.f - msk);
        }
        if (tid == 0) u.ph.sx[2 * TOPIC] = sv2;
        __syncthreads();
        int j = (bid - 420) * 8 + warp;
        const float* row = Wih + j * GRUIN;
        float p = 0.f;
        for (int i = lane; i < GRUIN; i += 32) p += row[i] * u.ph.sx[i];
        p = warpSum(p);
        if (lane == 0) g_gsum[j] = p;
        __syncthreads();
        if (tid == 0) { __threadfence(); atomicAdd(&g_cntG, 1); }
    } else if (bid == 516) {
        // ---- alpha = softmax(alog) ----
        if (tid == 0) { while (VLOAD(g_cntL) < 128) {} __threadfence(); }
        __syncthreads();
        float l[4];
        #pragma unroll
        for (int j = 0; j < 4; j++) l[j] = g_alog[tid + 256 * j];
        float m = fmaxf(fmaxf(l[0], l[1]), fmaxf(l[2], l[3]));
        m = warpMax(m);
        if (lane == 0) u.ph.red[warp] = m;
        __syncthreads();
        if (tid == 0) {
            float mm = u.ph.red[0];
            #pragma unroll
            for (int w = 1; w < 8; w++) mm = fmaxf(mm, u.ph.red[w]);
            u.ph.sbc = mm;
        }
        __syncthreads();
        float M = u.ph.sbc;
        float e[4], es = 0.f;
        #pragma unroll
        for (int j = 0; j < 4; j++) { e[j] = expf(l[j] - M); es += e[j]; }
        es = warpSum(es);
        if (lane == 0) u.ph.red[warp] = es;
        __syncthreads();
        if (tid == 0) {
            float ss = 0.f;
            #pragma unroll
            for (int w = 0; w < 8; w++) ss += u.ph.red[w];
            u.ph.sbc = ss;
        }
        __syncthreads();
        float inv = 1.f / u.ph.sbc;
        #pragma unroll
        for (int j = 0; j < 4; j++) g_alpha[tid + 256 * j] = e[j] * inv;
        __syncthreads();
        if (tid == 0) { __threadfence(); VLOAD(g_fAlpha) = 1; }
    } else if (bid == 517) {
        // ---- radix-select top-64 + softmax ----
        if (tid == 0) { while (VLOAD(g_cntV) < 128) {} __threadfence(); }
        if (tid < 32) u.ph.sc[tid] = 0;
        if (tid == 0) u.ph.sslot = 0;
        __syncthreads();
        unsigned key[4]; float val[4];
        #pragma unroll
        for (int j = 0; j < 4; j++) {
            float f = g_beta_all[tid + 256 * j];
            val[j] = f;
            unsigned uu = __float_as_uint(f);
            key[j] = (uu & 0x80000000u) ? ~uu : (uu | 0x80000000u);
        }
        unsigned T = 0;
        #pragma unroll
        for (int bit = 31; bit >= 0; bit--) {
            unsigned cand = T | (1u << bit);
            int c = (key[0] >= cand) + (key[1] >= cand) + (key[2] >= cand) + (key[3] >= cand);
            c = __reduce_add_sync(0xffffffffu, c);
            if (lane == 0) atomicAdd(&u.ph.sc[bit], c);
            __syncthreads();
            if (u.ph.sc[bit] >= TOPK) T = cand;
        }
        #pragma unroll
        for (int j = 0; j < 4; j++) {
            if (key[j] > T) {
                int p = atomicAdd(&u.ph.sslot, 1);
                u.ph.sval[p] = val[j]; u.ph.sidx[p] = tid + 256 * j;
            }
        }
        __syncthreads();
        #pragma unroll
        for (int j = 0; j < 4; j++) {
            if (key[j] == T) {
                int p = atomicAdd(&u.ph.sslot, 1);
                if (p < TOPK) { u.ph.sval[p] = val[j]; u.ph.sidx[p] = tid + 256 * j; }
            }
        }
        __syncthreads();
        if (tid < TOPK) {
            float m = warpMax(u.ph.sval[tid]);
            if (lane == 0) u.ph.sred[tid >> 5] = m;
        }
        __syncthreads();
        float M2 = fmaxf(u.ph.sred[0], u.ph.sred[1]);
        float e2 = 0.f;
        if (tid < TOPK) {
            e2 = expf(u.ph.sval[tid] - M2);
            float ss = warpSum(e2);
            if (lane == 0) u.ph.sred[2 + (tid >> 5)] = ss;
        }
        __syncthreads();
        if (tid < TOPK) {
            g_beta[tid] = e2 / (u.ph.sred[2] + u.ph.sred[3]);
            g_idx[tid]  = u.ph.sidx[tid];
        }
        __syncthreads();
        if (tid == 0) { __threadfence(); VLOAD(g_fTop) = 1; }
    } else if (bid < BID_GATH) {
        // ---------------- GEMM tile: 64 k-rows x 32 cols x 3 gates ----------------
        int id = bid - BID_GEMM;           // 0..127
        int k0 = (id & 15) * 64;
        int c0 = (id >> 4) * 32;
        int tx = tid & 15, ty = tid >> 4;
        int tx2 = tx * 2, ty4 = ty * 4;

        int am = tid >> 2, adq = tid & 3;
        int l0 = tid, l1 = tid + 256;
        int bg0 = l0 >> 7, br0 = (l0 >> 2) & 31, bq0 = l0 & 3;
        int bg1 = l1 >> 7, br1 = (l1 >> 2) & 31, bq1 = l1 & 3;
        bool bact1 = (tid < 128);

        float acc[3][8];
        #pragma unroll
        for (int g = 0; g < 3; g++)
            #pragma unroll
            for (int q = 0; q < 8; q++) acc[g][q] = 0.f;

        const float* aptr  = h0 + (k0 + am) * HDIM + adq * 4;
        const float* bptr0 = Whh + (bg0 * HDIM + c0 + br0) * HDIM + bq0 * 4;
        const float* bptr1 = Whh + (bg1 * HDIM + c0 + br1) * HDIM + bq1 * 4;

        float4 av  = *(const float4*)(aptr);
        float4 bv0 = *(const float4*)(bptr0);
        float4 bv1 = bact1 ? *(const float4*)(bptr1) : make_float4(0, 0, 0, 0);

        for (int kk = 0; kk < 16; kk++) {
            u.g.As[adq * 4 + 0][am] = av.x;
            u.g.As[adq * 4 + 1][am] = av.y;
            u.g.As[adq * 4 + 2][am] = av.z;
            u.g.As[adq * 4 + 3][am] = av.w;
            u.g.Bs[bg0][bq0 * 4 + 0][br0] = bv0.x;
            u.g.Bs[bg0][bq0 * 4 + 1][br0] = bv0.y;
            u.g.Bs[bg0][bq0 * 4 + 2][br0] = bv0.z;
            u.g.Bs[bg0][bq0 * 4 + 3][br0] = bv0.w;
            if (bact1) {
                u.g.Bs[bg1][bq1 * 4 + 0][br1] = bv1.x;
                u.g.Bs[bg1][bq1 * 4 + 1][br1] = bv1.y;
                u.g.Bs[bg1][bq1 * 4 + 2][br1] = bv1.z;
                u.g.Bs[bg1][bq1 * 4 + 3][br1] = bv1.w;
            }
            __syncthreads();
            if (kk < 15) {
                av  = *(const float4*)(aptr + (kk + 1) * 16);
                bv0 = *(const float4*)(bptr0 + (kk + 1) * 16);
                if (bact1) bv1 = *(const float4*)(bptr1 + (kk + 1) * 16);
            }
            #pragma unroll
            for (int d = 0; d < 16; d++) {
                float4 a4 = *(const float4*)&u.g.As[d][ty4];
                float2 b0 = *(const float2*)&u.g.Bs[0][d][tx2];
                float2 b1 = *(const float2*)&u.g.Bs[1][d][tx2];
                float2 b2 = *(const float2*)&u.g.Bs[2][d][tx2];
                float a[4] = {a4.x, a4.y, a4.z, a4.w};
                #pragma unroll
                for (int m = 0; m < 4; m++) {
                    acc[0][m * 2 + 0] += a[m] * b0.x;
                    acc[0][m * 2 + 1] += a[m] * b0.y;
                    acc[1][m * 2 + 0] += a[m] * b1.x;
                    acc[1][m * 2 + 1] += a[m] * b1.y;
                    acc[2][m * 2 + 0] += a[m] * b2.x;
                    acc[2][m * 2 + 1] += a[m] * b2.y;
                }
            }
            __syncthreads();
        }

        // wait for gsum + alpha (ready long before the mainloop ends)
        if (tid == 0) { while (VLOAD(g_cntG) < 96 || VLOAD(g_fAlpha) == 0) {} __threadfence(); }
        __syncthreads();

        // epilogue
        #pragma unroll
        for (int cc = 0; cc < 2; cc++) {
            int c = c0 + tx2 + cc;
            float gsr = g_gsum[c],  gsz = g_gsum[HDIM + c],  gsn = g_gsum[2 * HDIM + c];
            float bir = bih[c],     biz = bih[HDIM + c],     bin_ = bih[2 * HDIM + c];
            float bhr = bhh[c],     bhz = bhh[HDIM + c],     bhn = bhh[2 * HDIM + c];
            #pragma unroll
            for (int m = 0; m < 4; m++) {
                int k = k0 + ty4 + m;
                float al = g_alpha[k];
                float rg = 1.f / (1.f + expf(-(al * gsr + bir + acc[0][m * 2 + cc] + bhr)));
                float zg = 1.f / (1.f + expf(-(al * gsz + biz + acc[1][m * 2 + cc] + bhz)));
                float ng = tanhf(al * gsn + bin_ + rg * (acc[2][m * 2 + cc] + bhn));
                float hv = h0[k * HDIM + c];
                out[1 + k * HDIM + c] = (1.f - zg) * ng + zg * hv;
            }
        }
        __syncthreads();
        if (tid == 0) { __threadfence(); atomicAdd(&g_gemmDone, 1); }
    } else {
        // ---------------- gather chunk ----------------
        int gid = bid - BID_GATH;          // 0..2047
        int i = gid >> 5;                  // topk index
        int ch = gid & 31;                 // 32-row chunk
        int kb = ch * 32;
        int col4 = tid & 63, rgrp = tid >> 6;

        if (tid == 0) { while (VLOAD(g_fTop) == 0 || VLOAD(g_fAlpha) == 0) {} __threadfence(); }
        __syncthreads();
        if (tid < 32) u.ga.salpha[tid] = g_alpha[kb + tid];
        __syncthreads();

        int t = g_idx[i];
        float betai = g_beta[i];
        const float* base = hs + (size_t)t * (KCNT * HDIM) + (size_t)kb * HDIM + col4 * 4;
        float4 acc = make_float4(0.f, 0.f, 0.f, 0.f);
        #pragma unroll
        for (int it = 0; it < 8; it++) {
            int rr = rgrp * 8 + it;
            float4 vv = *(const float4*)(base + (size_t)rr * HDIM);
            float a = u.ga.salpha[rr];
            acc.x += a * vv.x; acc.y += a * vv.y;
            acc.z += a * vv.z; acc.w += a * vv.w;
        }
        u.ga.part4[rgrp * 64 + col4] = acc;
        __syncthreads();
        const float* pf = (const float*)u.ga.part4;
        float sum = pf[tid] + pf[256 + tid] + pf[512 + tid] + pf[768 + tid];
        atomicAdd(&g_hkp_part[(gid & 7) * HDIM + tid], betai * sum);
        __threadfence();
        if (tid == 0) s_last = (atomicAdd(&g_gcnt, 1) == NGATH - 1) ? 1 : 0;
        __syncthreads();
        if (s_last) {
            __threadfence();
            float hk = 0.f;
            #pragma unroll
            for (int rr = 0; rr < 8; rr++) hk += __ldcg(&g_hkp_part[rr * HDIM + tid]);
            float p = Wsc[TOPIC + tid] * hk;
            if (tid < TOPIC) p += Wsc[tid] * g_v[tid];
            p = warpSum(p);
            if ((tid & 31) == 0) red2[tid >> 5] = p;
            __syncthreads();
            if (tid == 0) {
                float s2 = 0.f;
                #pragma unroll
                for (int w = 0; w < 8; w++) s2 += red2[w];
                out[0] = s2 + bsc[0];
                // wait for all GEMM blocks before resetting shared state
                while (VLOAD(g_gemmDone) < NG) {}
                g_cntAv = 0; g_cntAk = 0; g_cntV = 0; g_cntL = 0; g_cntG = 0;
                g_fAlpha = 0; g_fTop = 0; g_gcnt = 0; g_gemmDone = 0;
            }
            __syncthreads();
            #pragma unroll
            for (int rr = 0; rr < 8; rr++) g_hkp_part[rr * HDIM + tid] = 0.f;
        }
    }
}

extern "C" void kernel_launch(void* const* d_in, const int* in_sizes, int n_in,
                              void* d_out, int out_size) {
    const float* co_e = (const float*)d_in[0];
    const float* ex_e = (const float*)d_in[1];
    const float* s    = (const float*)d_in[2];
    const float* h    = (const float*)d_in[3];
    const float* vs   = (const float*)d_in[4];
    const float* hs   = (const float*)d_in[5];
    const float* Wr   = (const float*)d_in[6];
    const float* br   = (const float*)d_in[7];
    const float* Wk   = (const float*)d_in[8];
    const float* bk   = (const float*)d_in[9];
    const float* KM   = (const float*)d_in[10];
    const float* Wsc  = (const float*)d_in[11];
    const float* bsc  = (const float*)d_in[12];
    const float* Wih  = (const float*)d_in[13];
    const float* Whh  = (const float*)d_in[14];
    const float* bih  = (const float*)d_in[15];
    const float* bhh  = (const float*)d_in[16];
    float* out = (float*)d_out;

    fused<<<GRID, 256>>>(Wr, br, ex_e, Wk, bk, co_e, vs, KM, Wih, s,
                         hs, h, Whh, bih, bhh, Wsc, bsc, out);
}